// round 16
// baseline (speedup 1.0000x reference)
#include <cuda_runtime.h>
#include <math_constants.h>

#define NPTS   8192
#define BATCH  2
#define BN_TOT (BATCH*NPTS)      /* 16384 */
#define KNB    20
#define M2     (BN_TOT*KNB)      /* 327680 */
#define QPB    4                 /* queries per fused block */
#define RPB    (QPB*KNB)         /* 80 pair-rows per block */

typedef unsigned long long ull;

/* ------------------------- device scratch ------------------------- */
__device__ float g_xb[BN_TOT*64];
__device__ float g_v [BN_TOT*64];
__device__ int   g_idx[M2];
__device__ float g_qw[BN_TOT*256];
__device__ float g_kw[BN_TOT*256];
__device__ __align__(16) float g_w2cat[2*64*320];
__device__ __align__(16) float g_cvec[2*256];
__device__ __align__(16) float g_wcat[2*64*576];
__device__ unsigned g_pool[BATCH*64];

/* ------------------------- f32x2 helpers -------------------------- */
__device__ __forceinline__ void fma2(ull &d, ull a, ull b){
    asm("fma.rn.f32x2 %0, %1, %2, %0;" : "+l"(d) : "l"(a), "l"(b));
}
__device__ __forceinline__ ull dup2(float a){
    ull r; asm("mov.b64 %0, {%1, %1};" : "=l"(r) : "f"(a)); return r;
}
__device__ __forceinline__ float2 unpack2(ull v){
    float2 f; asm("mov.b64 {%0,%1}, %2;" : "=f"(f.x), "=f"(f.y) : "l"(v));
    return f;
}
/* order-monotone float <-> unsigned encoding for atomicMax pooling */
__device__ __forceinline__ unsigned fenc(float f){
    unsigned u = __float_as_uint(f);
    return (u & 0x80000000u) ? ~u : (u | 0x80000000u);
}
__device__ __forceinline__ float fdec(unsigned v){
    return (v & 0x80000000u) ? __uint_as_float(v & 0x7FFFFFFFu)
                             : __uint_as_float(~v);
}

/* ==== prep (450 blocks): w2cat, cvec, wcat + pool reset =========== */
__global__ __launch_bounds__(256) void prep_kernel(
    const float* __restrict__ qkv1, const float* __restrict__ pw2_1,
    const float* __restrict__ aw1_1, const float* __restrict__ pb2_1,
    const float* __restrict__ ab1_1,
    const float* __restrict__ qkv2, const float* __restrict__ pw2_2,
    const float* __restrict__ aw1_2, const float* __restrict__ pb2_2,
    const float* __restrict__ ab1_2)
{
    int r = blockIdx.x, t = threadIdx.x;     /* 0..449 */
    if (r == 0 && t < BATCH*64) g_pool[t] = 0u;
    int L  = r / 225;
    int rr = r % 225;
    const float* qkvw = L ? qkv2 : qkv1;
    const float* pw2  = L ? pw2_2 : pw2_1;
    const float* aw1  = L ? aw1_2 : aw1_1;
    const float* pb2  = L ? pb2_2 : pb2_1;
    const float* ab1  = L ? ab1_2 : ab1_1;
    float* w2 = g_w2cat + L*64*320;
    float* cv = g_cvec  + L*256;
    float* wc = g_wcat  + L*64*576;

    if (rr < 80){                       /* w2cat = [pw2 | pw2@aw1_bot] */
        int i = rr*256 + t;             /* 64*320 */
        int row = i / 320, c = i % 320;
        if (c < 64){
            w2[i] = pw2[row*64 + c];
        } else {
            int cc = c - 64;
            float s = 0.f;
            #pragma unroll 8
            for (int d=0; d<64; d++)
                s += pw2[row*64 + d] * aw1[(64+d)*256 + cc];
            w2[i] = s;
        }
    } else if (rr == 80){               /* cvec = ab1 + pb2@aw1_bot */
        float s = ab1[t];
        #pragma unroll 8
        for (int d=0; d<64; d++)
            s += pb2[d] * aw1[(64+d)*256 + t];
        cv[t] = s;
    } else {                            /* wcat = [Wv | Wq@aw1t | Wk@aw1t] */
        int i = (rr-81)*256 + t;        /* 64*576 */
        int row = i / 576, c = i % 576;
        float s;
        if (c < 64){
            s = qkvw[row*192 + 128 + c];            /* Wv */
        } else if (c < 320){
            int cc = c - 64;
            s = 0.f;
            #pragma unroll 8
            for (int d=0; d<64; d++)                /* Wq@aw1_top */
                s += qkvw[row*192 + d] * aw1[d*256 + cc];
        } else {
            int cc = c - 320;
            s = 0.f;
            #pragma unroll 8
            for (int d=0; d<64; d++)                /* Wk@aw1_top */
                s += qkvw[row*192 + 64 + d] * aw1[d*256 + cc];
        }
        wc[i] = s;
    }
}

/* ---------- KNN v8: 16 q/block, 16 splits, 1024 blocks ------------ */
#define KQ   16
#define KS   16
#define KCH  512                 /* candidates per split */
#define KBUF 15
#define KNN_BLKS (BN_TOT/KQ)     /* 1024 */
#define CMB_SMEM 64512           /* 32768 sp + 30720 buf + 1024 thrs */
#define INITKEY 0x7F800000FFFFFFFFULL

__device__ __forceinline__ void knn_body(const float* __restrict__ pts,
                                         int blk, char* smraw)
{
    float4* sp  = (float4*)smraw;               /* [2048] = 32768 B */
    ull* buf    = (ull*)(smraw + 32768);        /* [256*15] = 30720 B */
    float* thrs = (float*)(smraw + 63488);      /* [256] */

    int t = threadIdx.x;
    int s = t >> 4;                             /* split 0..15 */
    int qi = t & 15;                            /* query within block */
    int gq = blk*KQ + qi;
    int b  = gq >> 13;
    float qx = pts[gq*3+0], qy = pts[gq*3+1], qz = pts[gq*3+2];
    const float* cloud = pts + (size_t)b*NPTS*3;

    ull best[KNB];
    #pragma unroll
    for (int p=0;p<KNB;p++) best[p] = INITKEY;
    float thrq = CUDART_INF_F;
    int cnt = 0;
    thrs[t] = CUDART_INF_F;

    for (int iter = 0; iter < 4; iter++){
        __syncthreads();
        #pragma unroll
        for (int u=0; u<8; u++){
            int e = u*256 + t;                  /* 0..2047 */
            int s_e = e >> 7, c_e = e & 127;
            const float* pp = cloud + (size_t)(s_e*KCH + iter*128 + c_e)*3;
            sp[e] = make_float4(pp[0], pp[1], pp[2], 0.f);
        }
        __syncthreads();
        int base = s*128;
        int id0  = s*KCH + iter*128;
        for (int c8 = 0; c8 < 128; c8 += 8){
            if ((c8 & 31) == 0){        /* advisory union threshold */
                float m = thrs[qi];
                #pragma unroll
                for (int s2=1;s2<KS;s2++) m = fminf(m, thrs[s2*16 + qi]);
                thrq = fminf(thrq, m);
            }
            #pragma unroll
            for (int j=0;j<8;j++){
                float4 p = sp[base + c8 + j];
                float dx = qx-p.x, dy = qy-p.y, dz = qz-p.z;
                float d2 = fmaf(dx,dx,fmaf(dy,dy,dz*dz));
                if (d2 <= thrq){
                    ull key;
                    asm("mov.b64 %0, {%1, %2};" : "=l"(key)
                        : "r"(id0 + c8 + j), "r"(__float_as_uint(d2)));
                    buf[t*KBUF + cnt++] = key;
                }
            }
            if (__any_sync(0xffffffffu, cnt >= KBUF-7)){
                int n = cnt;
                for (int j2 = 0; j2 < n; j2++){
                    ull k2 = buf[t*KBUF + j2];
                    if (k2 < best[KNB-1]){
                        best[KNB-1] = k2;
                        #pragma unroll
                        for (int p = KNB-1; p >= 1; --p){
                            ull a = best[p-1], bb = best[p];
                            bool sw = bb < a;
                            best[p-1] = sw ? bb : a;
                            best[p]   = sw ? a : bb;
                        }
                    }
                }
                cnt = 0;
                float bd19 = __uint_as_float((unsigned)(best[KNB-1] >> 32));
                thrq = fminf(thrq, bd19);
                thrs[t] = bd19;
            }
        }
    }
    for (int j2 = 0; j2 < cnt; j2++){
        ull k2 = buf[t*KBUF + j2];
        if (k2 < best[KNB-1]){
            best[KNB-1] = k2;
            #pragma unroll
            for (int p = KNB-1; p >= 1; --p){
                ull a = best[p-1], bb = best[p];
                bool sw = bb < a;
                best[p-1] = sw ? bb : a;
                best[p]   = sw ? a : bb;
            }
        }
    }

    __syncthreads();
    ull* mrg = (ull*)smraw;                     /* [16*16*20] = 40960 B */
    #pragma unroll
    for (int p=0;p<KNB;p++) mrg[(qi*KS + s)*KNB + p] = best[p];
    __syncthreads();

    if (t < KQ){
        int ptr[KS];
        #pragma unroll
        for (int s2=0;s2<KS;s2++) ptr[s2] = 0;
        int outq = blk*KQ + t;
        #pragma unroll 1
        for (int r=0;r<KNB;r++){
            ull bk = ~0ULL; int bs = 0;
            #pragma unroll
            for (int s2=0;s2<KS;s2++){
                if (ptr[s2] < KNB){
                    ull k2 = mrg[(t*KS + s2)*KNB + ptr[s2]];
                    if (k2 < bk){ bk = k2; bs = s2; }
                }
            }
            ptr[bs]++;
            g_idx[outq*KNB + r] = (int)(unsigned)(bk & 0xFFFFFFFFULL);
        }
    }
}

/* ---- pg_body: [v|qW|kW] = x @ wcat tile (64x64, K=64), FFMA2 -----
   layer 0: A tile computed inline as relu(pts@conv_w + conv_b)     */
__device__ __forceinline__ void pg_body(int layer, int bm0, int by,
                                        const float* __restrict__ pts,
                                        const float* __restrict__ cw,
                                        const float* __restrict__ cb,
                                        char* smraw)
{
    float* As = (float*)smraw;              /* 64*68 = 17408 B */
    float* Bs = (float*)(smraw + 17408);    /* 16*64 =  4096 B */
    float* Cs = (float*)(smraw + 21504);    /* 256 floats = 1024 B */
    const float* W = g_wcat + layer*64*576;
    int t = threadIdx.x, tx = t & 15, ty = t >> 4;
    int n0 = by * 64;

    if (layer == 0){
        if (t < 192) Cs[t] = cw[t];
        else if (t < 256) Cs[t] = cb[t-192];
        __syncthreads();
        #pragma unroll
        for (int i=0;i<4;i++){
            int idx4 = t + i*256;
            int r = idx4 >> 4, c4 = idx4 & 15;
            int c = 4*c4;
            const float* pr = &pts[(size_t)(bm0+r)*3];
            float px = pr[0], py = pr[1], pz = pr[2];
            float4 o;
            o.x = fmaxf(fmaf(px, Cs[c+0], fmaf(py, Cs[64+c+0], fmaf(pz, Cs[128+c+0], Cs[192+c+0]))), 0.f);
            o.y = fmaxf(fmaf(px, Cs[c+1], fmaf(py, Cs[64+c+1], fmaf(pz, Cs[128+c+1], Cs[192+c+1]))), 0.f);
            o.z = fmaxf(fmaf(px, Cs[c+2], fmaf(py, Cs[64+c+2], fmaf(pz, Cs[128+c+2], Cs[192+c+2]))), 0.f);
            o.w = fmaxf(fmaf(px, Cs[c+3], fmaf(py, Cs[64+c+3], fmaf(pz, Cs[128+c+3], Cs[192+c+3]))), 0.f);
            *(float4*)&As[r*68 + 4*c4] = o;
        }
    } else {
        #pragma unroll
        for (int i=0;i<4;i++){
            int idx4 = t + i*256;
            int r = idx4 >> 4, c4 = idx4 & 15;
            *(float4*)&As[r*68 + 4*c4] =
                *(const float4*)&g_xb[(size_t)(bm0+r)*64 + 4*c4];
        }
    }

    ull acc2[4][2] = {};
    for (int ch=0; ch<64; ch+=16){
        __syncthreads();
        {
            int r = t >> 4, c4 = t & 15;
            *(float4*)&Bs[r*64 + 4*c4] = *(const float4*)&W[(ch+r)*576 + n0 + 4*c4];
        }
        __syncthreads();
        #pragma unroll
        for (int k4=0;k4<4;k4++){
            ulonglong2 b0 = *(const ulonglong2*)&Bs[(4*k4+0)*64 + 4*tx];
            ulonglong2 b1 = *(const ulonglong2*)&Bs[(4*k4+1)*64 + 4*tx];
            ulonglong2 b2 = *(const ulonglong2*)&Bs[(4*k4+2)*64 + 4*tx];
            ulonglong2 b3 = *(const ulonglong2*)&Bs[(4*k4+3)*64 + 4*tx];
            #pragma unroll
            for (int i=0;i<4;i++){
                float4 a = *(const float4*)&As[(4*ty+i)*68 + ch + 4*k4];
                ull ax = dup2(a.x), ay = dup2(a.y);
                ull az = dup2(a.z), aw = dup2(a.w);
                fma2(acc2[i][0], ax, b0.x); fma2(acc2[i][1], ax, b0.y);
                fma2(acc2[i][0], ay, b1.x); fma2(acc2[i][1], ay, b1.y);
                fma2(acc2[i][0], az, b2.x); fma2(acc2[i][1], az, b2.y);
                fma2(acc2[i][0], aw, b3.x); fma2(acc2[i][1], aw, b3.y);
            }
        }
    }
    float* outp; int stride, c0;
    if (by == 0){ outp = g_v;  stride = 64;  c0 = 0; }
    else if (by < 5){ outp = g_qw; stride = 256; c0 = (by-1)*64; }
    else { outp = g_kw; stride = 256; c0 = (by-5)*64; }
    #pragma unroll
    for (int i=0;i<4;i++){
        float2 lo = unpack2(acc2[i][0]), hi = unpack2(acc2[i][1]);
        float4 o = make_float4(lo.x, lo.y, hi.x, hi.y);
        *(float4*)&outp[(size_t)(bm0+4*ty+i)*stride + c0 + 4*tx] = o;
    }
}

/* ---- combo: knn (0..1023) + point_gemm L1 inline-embed ----------- */
__global__ __launch_bounds__(256) void knn_pg_kernel(
    const float* __restrict__ pts, const float* __restrict__ cw,
    const float* __restrict__ cb)
{
    extern __shared__ char smraw[];
    int blk = blockIdx.x;
    if (blk < KNN_BLKS){
        knn_body(pts, blk, smraw);
    } else {
        int i = blk - KNN_BLKS;             /* 0..2303 */
        pg_body(0, (i & 255)*64, i >> 8, pts, cw, cb, smraw);
    }
}

/* ---- standalone point_gemm (layer 2), 4 CTAs/SM ------------------ */
__global__ __launch_bounds__(256, 4) void point_gemm_kernel(void)
{
    __shared__ __align__(16) char smr[17408 + 4096 + 1024];
    pg_body(1, blockIdx.x*64, blockIdx.y, 0, 0, 0, smr);
}

/* ==== mega-fused: h1 -> H@W2cat FFMA2 -> softmax -> out/pool ====== */
#define SMF_B   0                       /* 2 x 16 x 68 = 2176        */
#define SMF_A   (SMF_B + 2176)          /* 80 x 68 = 5440            */
#define SMF_V   (SMF_A + RPB*68)        /* 80 x 68 = 5440            */
#define SMF_REL (SMF_V + RPB*68)        /* 80 x 4                    */
#define SMF_SIM (SMF_REL + RPB*4)       /* 80                        */
#define SMF_JR  (SMF_SIM + RPB)         /* 80                        */
#define SMF_PW  (SMF_JR + RPB)          /* 256                       */
#define SMF_Q   (SMF_PW + 256)          /* QPB x 256 = 1024          */
#define SMF_TOT ((SMF_Q + QPB*256) * 4)

__global__ __launch_bounds__(256, 3) void fused_attn_kernel(
    const float* __restrict__ pts,
    const float* __restrict__ pw1, const float* __restrict__ pb1,
    const float* __restrict__ pb2, const float* __restrict__ aw2,
    const float* __restrict__ ab2, int layer, int outsel)
{
    extern __shared__ float sm[];
    float* Bs  = sm + SMF_B;
    float* As  = sm + SMF_A;
    float* Vs  = sm + SMF_V;
    float* Rel = sm + SMF_REL;
    float* Sim = sm + SMF_SIM;
    int*   Jr  = (int*)(sm + SMF_JR);
    float* Pw  = sm + SMF_PW;
    float* Qs  = sm + SMF_Q;

    const float* W2 = g_w2cat + layer*64*320;
    const float* CV = g_cvec  + layer*256;

    int t = threadIdx.x, tx = t & 15, ty = t >> 4;
    int ldr = t >> 4, ldc = t & 15;
    int q0 = blockIdx.x * QPB;
    int m0 = q0 * KNB;

    if (t < 64){
        Pw[t]     = pw1[t];
        Pw[64+t]  = pw1[64+t];
        Pw[128+t] = pw1[128+t];
        Pw[192+t] = pb1[t];
    }
    if (t < RPB){
        int gq = q0 + t/KNB;
        int b  = gq >> 13;
        int jr = (b<<13) + g_idx[m0 + t];
        Jr[t] = jr;
        Rel[t*4+0] = pts[gq*3+0] - pts[(size_t)jr*3+0];
        Rel[t*4+1] = pts[gq*3+1] - pts[(size_t)jr*3+1];
        Rel[t*4+2] = pts[gq*3+2] - pts[(size_t)jr*3+2];
    }
    /* stage this block's 4 query rows of g_qw (1 float4 per thread) */
    *(float4*)&Qs[t*4] =
        *(const float4*)&g_qw[(size_t)(q0 + (t >> 6))*256 + (t & 63)*4];
    *(float4*)&Bs[ldr*68 + 4*ldc] = *(const float4*)&W2[ldr*320 + 4*ldc];
    __syncthreads();

    #pragma unroll
    for (int e = t; e < RPB*64; e += 256){
        int r = e >> 6, c = e & 63;
        float h = fmaf(Rel[r*4+0], Pw[c],
                  fmaf(Rel[r*4+1], Pw[64+c],
                  fmaf(Rel[r*4+2], Pw[128+c], Pw[192+c])));
        As[r*68 + c] = fmaxf(h, 0.f);
    }
    __syncthreads();

    int jr_r[5], qx_r[5];
    #pragma unroll
    for (int i=0;i<5;i++){
        int r = ty*5 + i;
        jr_r[i] = Jr[r];
        qx_r[i] = (r/KNB)*256;
    }

    float rsum[5] = {0.f,0.f,0.f,0.f,0.f};
    ull acc2[5][2];
    for (int it = 0; it < 20; it++){
        int nb = it >> 2, ch = (it & 3) * 16;
        int cur = it & 1;
        float4 nxt;
        if (it < 19){
            int nit = it + 1, nnb = nit >> 2, nch = (nit & 3) * 16;
            nxt = *(const float4*)&W2[(nch+ldr)*320 + nnb*64 + 4*ldc];
        }
        if ((it & 3) == 0){
            #pragma unroll
            for (int i=0;i<5;i++){ acc2[i][0] = 0ULL; acc2[i][1] = 0ULL; }
        }
        const float* Bc = &Bs[cur*1088];
        #pragma unroll
        for (int k4=0;k4<4;k4++){
            ulonglong2 b0 = *(const ulonglong2*)&Bc[(4*k4+0)*68 + 4*tx];
            ulonglong2 b1 = *(const ulonglong2*)&Bc[(4*k4+1)*68 + 4*tx];
            ulonglong2 b2 = *(const ulonglong2*)&Bc[(4*k4+2)*68 + 4*tx];
            ulonglong2 b3 = *(const ulonglong2*)&Bc[(4*k4+3)*68 + 4*tx];
            #pragma unroll
            for (int i=0;i<5;i++){
                float4 a = *(const float4*)&As[(ty*5+i)*68 + ch + 4*k4];
                ull ax = dup2(a.x), ay = dup2(a.y);
                ull az = dup2(a.z), aw = dup2(a.w);
                fma2(acc2[i][0], ax, b0.x); fma2(acc2[i][1], ax, b0.y);
                fma2(acc2[i][0], ay, b1.x); fma2(acc2[i][1], ay, b1.y);
                fma2(acc2[i][0], az, b2.x); fma2(acc2[i][1], az, b2.y);
                fma2(acc2[i][0], aw, b3.x); fma2(acc2[i][1], aw, b3.y);
            }
        }
        if ((it & 3) == 3){
            if (nb == 0){
                float4 pb = *(const float4*)&pb2[4*tx];
                #pragma unroll
                for (int i=0;i<5;i++){
                    int r = ty*5 + i;
                    float2 lo = unpack2(acc2[i][0]);
                    float2 hi = unpack2(acc2[i][1]);
                    float4 vv = *(const float4*)&g_v[(size_t)jr_r[i]*64 + 4*tx];
                    float4 o = make_float4(lo.x+pb.x+vv.x, lo.y+pb.y+vv.y,
                                           hi.x+pb.z+vv.z, hi.y+pb.w+vv.w);
                    *(float4*)&Vs[r*68 + 4*tx] = o;
                }
            } else {
                int cb = (nb-1)*64 + 4*tx;
                float4 cv  = *(const float4*)&CV[cb];
                float4 a2v = *(const float4*)&aw2[cb];
                #pragma unroll
                for (int i=0;i<5;i++){
                    float2 lo = unpack2(acc2[i][0]);
                    float2 hi = unpack2(acc2[i][1]);
                    float4 qv = *(const float4*)&Qs[qx_r[i] + cb];
                    float4 kv = *(const float4*)&g_kw[(size_t)jr_r[i]*256 + cb];
                    float h0 = fmaxf(lo.x + cv.x + qv.x - kv.x, 0.f);
                    float h1 = fmaxf(lo.y + cv.y + qv.y - kv.y, 0.f);
                    float h2 = fmaxf(hi.x + cv.z + qv.z - kv.z, 0.f);
                    float h3 = fmaxf(hi.y + cv.w + qv.w - kv.w, 0.f);
                    rsum[i] += h0*a2v.x + h1*a2v.y + h2*a2v.z + h3*a2v.w;
                }
            }
        }
        if (it < 19){
            *(float4*)&Bs[(cur^1)*1088 + ldr*68 + 4*ldc] = nxt;
            __syncthreads();
        }
    }
    float abias = ab2[0];
    #pragma unroll
    for (int i=0;i<5;i++){
        float v = rsum[i];
        v += __shfl_xor_sync(0xffffffffu, v, 8);
        v += __shfl_xor_sync(0xffffffffu, v, 4);
        v += __shfl_xor_sync(0xffffffffu, v, 2);
        v += __shfl_xor_sync(0xffffffffu, v, 1);
        if (tx == 0) Sim[ty*5+i] = v + abias;
    }
    __syncthreads();

    if (t < 128){
        int w = t >> 5, lane = t & 31;
        float s = (lane < KNB) ? Sim[w*KNB + lane] : -CUDART_INF_F;
        float m = s;
        #pragma unroll
        for (int off=16; off; off>>=1) m = fmaxf(m, __shfl_xor_sync(0xffffffffu, m, off));
        float e = (lane < KNB) ? expf(s - m) : 0.f;
        float sum = e;
        #pragma unroll
        for (int off=16; off; off>>=1) sum += __shfl_xor_sync(0xffffffffu, sum, off);
        float attn = e / sum;
        float acc0 = 0.f, acc1 = 0.f;
        #pragma unroll
        for (int kk=0; kk<KNB; kk++){
            float a = __shfl_sync(0xffffffffu, attn, kk);
            const float* vb = &Vs[(w*KNB + kk)*68];
            acc0 += a * vb[lane];
            acc1 += a * vb[32 + lane];
        }
        if (outsel){
            g_xb[(size_t)(q0+w)*64 + lane]      = acc0;
            g_xb[(size_t)(q0+w)*64 + 32 + lane] = acc1;
        } else {
            int b = (q0+w) >> 13;
            atomicMax(&g_pool[b*64 + lane],      fenc(acc0));
            atomicMax(&g_pool[b*64 + 32 + lane], fenc(acc1));
        }
    }
}

/* ---------------- head: pooled max -> fc1(relu) -> fc3 ------------ */
__global__ void head_kernel(
    const float* __restrict__ fc1w, const float* __restrict__ fc1b,
    const float* __restrict__ fc3w, const float* __restrict__ fc3b,
    float* __restrict__ out)
{
    __shared__ float sp[BATCH*64];
    __shared__ float sh[BATCH*32];
    int t = threadIdx.x;
    if (t < 128) sp[t] = fdec(g_pool[t]);
    __syncthreads();
    if (t < 64){
        int b = t >> 5, cc = t & 31;
        float s = fc1b[cc];
        for (int c=0;c<64;c++) s += sp[b*64+c] * fc1w[c*32 + cc];
        sh[b*32 + cc] = fmaxf(s, 0.f);
    }
    __syncthreads();
    if (t < 6){
        int b = t / 3, o = t % 3;
        float s = fc3b[o];
        for (int cc=0;cc<32;cc++) s += sh[b*32+cc] * fc3w[cc*3 + o];
        out[b*3 + o] = s;
    }
}

/* ------------------------------ launch ---------------------------- */
extern "C" void kernel_launch(void* const* d_in, const int* in_sizes, int n_in,
                              void* d_out, int out_size)
{
    (void)in_sizes; (void)n_in; (void)out_size;
    const float* pts = (const float*)d_in[0];
    float* out = (float*)d_out;

    cudaFuncSetAttribute(fused_attn_kernel,
                         cudaFuncAttributeMaxDynamicSharedMemorySize, SMF_TOT);
    cudaFuncSetAttribute(knn_pg_kernel,
                         cudaFuncAttributeMaxDynamicSharedMemorySize, CMB_SMEM);

    const float* W1[9] = {
        (const float*)d_in[3], (const float*)d_in[4], (const float*)d_in[5],
        (const float*)d_in[6], (const float*)d_in[7], (const float*)d_in[8],
        (const float*)d_in[9], (const float*)d_in[10], (const float*)d_in[11]};
    const float* W2[9] = {
        (const float*)d_in[12], (const float*)d_in[13], (const float*)d_in[14],
        (const float*)d_in[15], (const float*)d_in[16], (const float*)d_in[17],
        (const float*)d_in[18], (const float*)d_in[19], (const float*)d_in[20]};

    /* #1 prep(+pool reset); #2 knn+pgL1; #3 fused L1; #4 pg L2;
       #5 fused L2 (+pool atomics); #6 head                          */
    prep_kernel<<<450, 256>>>(W1[0], W1[3], W1[5], W1[4], W1[6],
                              W2[0], W2[3], W2[5], W2[4], W2[6]);
    knn_pg_kernel<<<KNN_BLKS + 2304, 256, CMB_SMEM>>>(
        pts, (const float*)d_in[1], (const float*)d_in[2]);
    fused_attn_kernel<<<BN_TOT/QPB, 256, SMF_TOT>>>(
        pts, W1[1], W1[2], W1[4], W1[7], W1[8], 0, 1);

    point_gemm_kernel<<<dim3(BN_TOT/64, 9), 256>>>();
    fused_attn_kernel<<<BN_TOT/QPB, 256, SMF_TOT>>>(
        pts, W2[1], W2[2], W2[4], W2[7], W2[8], 1, 0);

    head_kernel<<<1, 128>>>((const float*)d_in[21], (const float*)d_in[22],
                            (const float*)d_in[23], (const float*)d_in[24], out);
}

// round 17
// speedup vs baseline: 1.0979x; 1.0979x over previous
#include <cuda_runtime.h>
#include <math_constants.h>

#define NPTS   8192
#define BATCH  2
#define BN_TOT (BATCH*NPTS)      /* 16384 */
#define KNB    20
#define M2     (BN_TOT*KNB)      /* 327680 */
#define QPB    4                 /* queries per fused block */
#define RPB    (QPB*KNB)         /* 80 pair-rows per block */

typedef unsigned long long ull;

/* ------------------------- device scratch ------------------------- */
__device__ float g_xb[BN_TOT*64];
__device__ float g_v [BN_TOT*64];
__device__ int   g_idx[M2];
__device__ float g_qw[BN_TOT*256];
__device__ float g_kw[BN_TOT*256];
__device__ __align__(16) float g_w2cat[2*64*320];
__device__ __align__(16) float g_cvec[2*256];
__device__ __align__(16) float g_wcat[2*64*576];
__device__ unsigned g_pool[BATCH*64];

/* ------------------------- f32x2 helpers -------------------------- */
__device__ __forceinline__ void fma2(ull &d, ull a, ull b){
    asm("fma.rn.f32x2 %0, %1, %2, %0;" : "+l"(d) : "l"(a), "l"(b));
}
__device__ __forceinline__ ull dup2(float a){
    ull r; asm("mov.b64 %0, {%1, %1};" : "=l"(r) : "f"(a)); return r;
}
__device__ __forceinline__ float2 unpack2(ull v){
    float2 f; asm("mov.b64 {%0,%1}, %2;" : "=f"(f.x), "=f"(f.y) : "l"(v));
    return f;
}
/* order-monotone float <-> unsigned encoding for atomicMax pooling */
__device__ __forceinline__ unsigned fenc(float f){
    unsigned u = __float_as_uint(f);
    return (u & 0x80000000u) ? ~u : (u | 0x80000000u);
}
__device__ __forceinline__ float fdec(unsigned v){
    return (v & 0x80000000u) ? __uint_as_float(v & 0x7FFFFFFFu)
                             : __uint_as_float(~v);
}

/* ==== prep (450 blocks): w2cat, cvec, wcat + pool reset =========== */
__global__ __launch_bounds__(256) void prep_kernel(
    const float* __restrict__ qkv1, const float* __restrict__ pw2_1,
    const float* __restrict__ aw1_1, const float* __restrict__ pb2_1,
    const float* __restrict__ ab1_1,
    const float* __restrict__ qkv2, const float* __restrict__ pw2_2,
    const float* __restrict__ aw1_2, const float* __restrict__ pb2_2,
    const float* __restrict__ ab1_2)
{
    int r = blockIdx.x, t = threadIdx.x;     /* 0..449 */
    if (r == 0 && t < BATCH*64) g_pool[t] = 0u;
    int L  = r / 225;
    int rr = r % 225;
    const float* qkvw = L ? qkv2 : qkv1;
    const float* pw2  = L ? pw2_2 : pw2_1;
    const float* aw1  = L ? aw1_2 : aw1_1;
    const float* pb2  = L ? pb2_2 : pb2_1;
    const float* ab1  = L ? ab1_2 : ab1_1;
    float* w2 = g_w2cat + L*64*320;
    float* cv = g_cvec  + L*256;
    float* wc = g_wcat  + L*64*576;

    if (rr < 80){                       /* w2cat = [pw2 | pw2@aw1_bot] */
        int i = rr*256 + t;             /* 64*320 */
        int row = i / 320, c = i % 320;
        if (c < 64){
            w2[i] = pw2[row*64 + c];
        } else {
            int cc = c - 64;
            float s = 0.f;
            #pragma unroll 8
            for (int d=0; d<64; d++)
                s += pw2[row*64 + d] * aw1[(64+d)*256 + cc];
            w2[i] = s;
        }
    } else if (rr == 80){               /* cvec = ab1 + pb2@aw1_bot */
        float s = ab1[t];
        #pragma unroll 8
        for (int d=0; d<64; d++)
            s += pb2[d] * aw1[(64+d)*256 + t];
        cv[t] = s;
    } else {                            /* wcat = [Wv | Wq@aw1t | Wk@aw1t] */
        int i = (rr-81)*256 + t;        /* 64*576 */
        int row = i / 576, c = i % 576;
        float s;
        if (c < 64){
            s = qkvw[row*192 + 128 + c];            /* Wv */
        } else if (c < 320){
            int cc = c - 64;
            s = 0.f;
            #pragma unroll 8
            for (int d=0; d<64; d++)                /* Wq@aw1_top */
                s += qkvw[row*192 + d] * aw1[d*256 + cc];
        } else {
            int cc = c - 320;
            s = 0.f;
            #pragma unroll 8
            for (int d=0; d<64; d++)                /* Wk@aw1_top */
                s += qkvw[row*192 + 64 + d] * aw1[d*256 + cc];
        }
        wc[i] = s;
    }
}

/* ---------- KNN (round-15 proven): 32 q/block, 8 splits ----------- */
#define KQ   32
#define KS   8
#define KCH  1024
#define KBUF 15
#define CMB_SMEM 64512           /* 32768 sp + 30720 buf + 1024 thrs */
#define INITKEY 0x7F800000FFFFFFFFULL

__device__ __forceinline__ void knn_body(const float* __restrict__ pts,
                                         int blk, char* smraw)
{
    float4* sp  = (float4*)smraw;               /* [2048] = 32768 B */
    ull* buf    = (ull*)(smraw + 32768);        /* [256*15] = 30720 B */
    float* thrs = (float*)(smraw + 63488);      /* [256] */

    int t = threadIdx.x;
    int s = t >> 5;                             /* warp = split 0..7 */
    int qi = t & 31;
    int gq = blk*KQ + qi;
    int b  = gq >> 13;
    float qx = pts[gq*3+0], qy = pts[gq*3+1], qz = pts[gq*3+2];
    const float* cloud = pts + (size_t)b*NPTS*3;

    ull best[KNB];
    #pragma unroll
    for (int p=0;p<KNB;p++) best[p] = INITKEY;
    float thrq = CUDART_INF_F;
    int cnt = 0;
    thrs[t] = CUDART_INF_F;

    for (int iter = 0; iter < KCH/256; iter++){
        __syncthreads();
        #pragma unroll
        for (int u=0; u<8; u++){
            const float* pp = cloud + (size_t)(u*KCH + iter*256 + t)*3;
            sp[u*256 + t] = make_float4(pp[0], pp[1], pp[2], 0.f);
        }
        __syncthreads();
        int base = s*256;
        int id0  = s*KCH + iter*256;
        for (int c8 = 0; c8 < 256; c8 += 8){
            if ((c8 & 31) == 0){        /* advisory union threshold */
                float m0 = fminf(fminf(thrs[qi],     thrs[qi+32]),
                                 fminf(thrs[qi+64],  thrs[qi+96]));
                float m1 = fminf(fminf(thrs[qi+128], thrs[qi+160]),
                                 fminf(thrs[qi+192], thrs[qi+224]));
                thrq = fminf(thrq, fminf(m0, m1));
            }
            #pragma unroll
            for (int j=0;j<8;j++){
                float4 p = sp[base + c8 + j];
                float dx = qx-p.x, dy = qy-p.y, dz = qz-p.z;
                float d2 = fmaf(dx,dx,fmaf(dy,dy,dz*dz));
                if (d2 <= thrq){
                    ull key;
                    asm("mov.b64 %0, {%1, %2};" : "=l"(key)
                        : "r"(id0 + c8 + j), "r"(__float_as_uint(d2)));
                    buf[t*KBUF + cnt++] = key;
                }
            }
            if (__any_sync(0xffffffffu, cnt >= KBUF-7)){
                int n = cnt;
                for (int j2 = 0; j2 < n; j2++){
                    ull k2 = buf[t*KBUF + j2];
                    if (k2 < best[KNB-1]){
                        best[KNB-1] = k2;
                        #pragma unroll
                        for (int p = KNB-1; p >= 1; --p){
                            ull a = best[p-1], bb = best[p];
                            bool sw = bb < a;
                            best[p-1] = sw ? bb : a;
                            best[p]   = sw ? a : bb;
                        }
                    }
                }
                cnt = 0;
                float bd19 = __uint_as_float((unsigned)(best[KNB-1] >> 32));
                thrq = fminf(thrq, bd19);
                thrs[t] = bd19;
            }
        }
    }
    for (int j2 = 0; j2 < cnt; j2++){
        ull k2 = buf[t*KBUF + j2];
        if (k2 < best[KNB-1]){
            best[KNB-1] = k2;
            #pragma unroll
            for (int p = KNB-1; p >= 1; --p){
                ull a = best[p-1], bb = best[p];
                bool sw = bb < a;
                best[p-1] = sw ? bb : a;
                best[p]   = sw ? a : bb;
            }
        }
    }

    __syncthreads();
    ull* mrg = (ull*)smraw;                     /* [32*8*20] = 40960 B */
    #pragma unroll
    for (int p=0;p<KNB;p++) mrg[(qi*KS + s)*KNB + p] = best[p];
    __syncthreads();

    if (t < KQ){
        int ptr[KS] = {0,0,0,0,0,0,0,0};
        int outq = blk*KQ + t;
        #pragma unroll 1
        for (int r=0;r<KNB;r++){
            ull bk = ~0ULL; int bs = 0;
            #pragma unroll
            for (int s2=0;s2<KS;s2++){
                if (ptr[s2] < KNB){
                    ull k2 = mrg[(t*KS + s2)*KNB + ptr[s2]];
                    if (k2 < bk){ bk = k2; bs = s2; }
                }
            }
            ptr[bs]++;
            g_idx[outq*KNB + r] = (int)(unsigned)(bk & 0xFFFFFFFFULL);
        }
    }
}

/* ---- pg_body: [v|qW|kW] = x @ wcat tile (64x64, K=64), FFMA2 -----
   layer 0: A tile computed inline as relu(pts@conv_w + conv_b)     */
__device__ __forceinline__ void pg_body(int layer, int bm0, int by,
                                        const float* __restrict__ pts,
                                        const float* __restrict__ cw,
                                        const float* __restrict__ cb,
                                        char* smraw)
{
    float* As = (float*)smraw;              /* 64*68 = 17408 B */
    float* Bs = (float*)(smraw + 17408);    /* 16*64 =  4096 B */
    float* Cs = (float*)(smraw + 21504);    /* 256 floats = 1024 B */
    const float* W = g_wcat + layer*64*576;
    int t = threadIdx.x, tx = t & 15, ty = t >> 4;
    int n0 = by * 64;

    if (layer == 0){
        if (t < 192) Cs[t] = cw[t];
        else if (t < 256) Cs[t] = cb[t-192];
        __syncthreads();
        #pragma unroll
        for (int i=0;i<4;i++){
            int idx4 = t + i*256;
            int r = idx4 >> 4, c4 = idx4 & 15;
            int c = 4*c4;
            const float* pr = &pts[(size_t)(bm0+r)*3];
            float px = pr[0], py = pr[1], pz = pr[2];
            float4 o;
            o.x = fmaxf(fmaf(px, Cs[c+0], fmaf(py, Cs[64+c+0], fmaf(pz, Cs[128+c+0], Cs[192+c+0]))), 0.f);
            o.y = fmaxf(fmaf(px, Cs[c+1], fmaf(py, Cs[64+c+1], fmaf(pz, Cs[128+c+1], Cs[192+c+1]))), 0.f);
            o.z = fmaxf(fmaf(px, Cs[c+2], fmaf(py, Cs[64+c+2], fmaf(pz, Cs[128+c+2], Cs[192+c+2]))), 0.f);
            o.w = fmaxf(fmaf(px, Cs[c+3], fmaf(py, Cs[64+c+3], fmaf(pz, Cs[128+c+3], Cs[192+c+3]))), 0.f);
            *(float4*)&As[r*68 + 4*c4] = o;
        }
    } else {
        #pragma unroll
        for (int i=0;i<4;i++){
            int idx4 = t + i*256;
            int r = idx4 >> 4, c4 = idx4 & 15;
            *(float4*)&As[r*68 + 4*c4] =
                *(const float4*)&g_xb[(size_t)(bm0+r)*64 + 4*c4];
        }
    }

    ull acc2[4][2] = {};
    for (int ch=0; ch<64; ch+=16){
        __syncthreads();
        {
            int r = t >> 4, c4 = t & 15;
            *(float4*)&Bs[r*64 + 4*c4] = *(const float4*)&W[(ch+r)*576 + n0 + 4*c4];
        }
        __syncthreads();
        #pragma unroll
        for (int k4=0;k4<4;k4++){
            ulonglong2 b0 = *(const ulonglong2*)&Bs[(4*k4+0)*64 + 4*tx];
            ulonglong2 b1 = *(const ulonglong2*)&Bs[(4*k4+1)*64 + 4*tx];
            ulonglong2 b2 = *(const ulonglong2*)&Bs[(4*k4+2)*64 + 4*tx];
            ulonglong2 b3 = *(const ulonglong2*)&Bs[(4*k4+3)*64 + 4*tx];
            #pragma unroll
            for (int i=0;i<4;i++){
                float4 a = *(const float4*)&As[(4*ty+i)*68 + ch + 4*k4];
                ull ax = dup2(a.x), ay = dup2(a.y);
                ull az = dup2(a.z), aw = dup2(a.w);
                fma2(acc2[i][0], ax, b0.x); fma2(acc2[i][1], ax, b0.y);
                fma2(acc2[i][0], ay, b1.x); fma2(acc2[i][1], ay, b1.y);
                fma2(acc2[i][0], az, b2.x); fma2(acc2[i][1], az, b2.y);
                fma2(acc2[i][0], aw, b3.x); fma2(acc2[i][1], aw, b3.y);
            }
        }
    }
    float* outp; int stride, c0;
    if (by == 0){ outp = g_v;  stride = 64;  c0 = 0; }
    else if (by < 5){ outp = g_qw; stride = 256; c0 = (by-1)*64; }
    else { outp = g_kw; stride = 256; c0 = (by-5)*64; }
    #pragma unroll
    for (int i=0;i<4;i++){
        float2 lo = unpack2(acc2[i][0]), hi = unpack2(acc2[i][1]);
        float4 o = make_float4(lo.x, lo.y, hi.x, hi.y);
        *(float4*)&outp[(size_t)(bm0+4*ty+i)*stride + c0 + 4*tx] = o;
    }
}

/* ---- combo: knn (0..511) + point_gemm L1 inline-embed (512..2815) */
__global__ __launch_bounds__(256) void knn_pg_kernel(
    const float* __restrict__ pts, const float* __restrict__ cw,
    const float* __restrict__ cb)
{
    extern __shared__ char smraw[];
    int blk = blockIdx.x;
    if (blk < 512){
        knn_body(pts, blk, smraw);
    } else {
        int i = blk - 512;                  /* 0..2303 */
        pg_body(0, (i & 255)*64, i >> 8, pts, cw, cb, smraw);
    }
}

/* ---- standalone point_gemm (layer 2), 4 CTAs/SM (r16 proven) ----- */
__global__ __launch_bounds__(256, 4) void point_gemm_kernel(void)
{
    __shared__ __align__(16) char smr[17408 + 4096 + 1024];
    pg_body(1, blockIdx.x*64, blockIdx.y, 0, 0, 0, smr);
}

/* ==== mega-fused: h1 -> H@W2cat FFMA2 -> softmax -> out/pool ====== */
#define SMF_B   0                       /* 2 x 16 x 68 = 2176        */
#define SMF_A   (SMF_B + 2176)          /* 80 x 68 = 5440            */
#define SMF_V   (SMF_A + RPB*68)        /* 80 x 68 = 5440            */
#define SMF_REL (SMF_V + RPB*68)        /* 80 x 4                    */
#define SMF_SIM (SMF_REL + RPB*4)       /* 80                        */
#define SMF_JR  (SMF_SIM + RPB)         /* 80                        */
#define SMF_PW  (SMF_JR + RPB)          /* 256                       */
#define SMF_Q   (SMF_PW + 256)          /* QPB x 256 = 1024          */
#define SMF_TOT ((SMF_Q + QPB*256) * 4)

__global__ __launch_bounds__(256, 3) void fused_attn_kernel(
    const float* __restrict__ pts,
    const float* __restrict__ pw1, const float* __restrict__ pb1,
    const float* __restrict__ pb2, const float* __restrict__ aw2,
    const float* __restrict__ ab2, int layer, int outsel)
{
    extern __shared__ float sm[];
    float* Bs  = sm + SMF_B;
    float* As  = sm + SMF_A;
    float* Vs  = sm + SMF_V;
    float* Rel = sm + SMF_REL;
    float* Sim = sm + SMF_SIM;
    int*   Jr  = (int*)(sm + SMF_JR);
    float* Pw  = sm + SMF_PW;
    float* Qs  = sm + SMF_Q;

    const float* W2 = g_w2cat + layer*64*320;
    const float* CV = g_cvec  + layer*256;

    int t = threadIdx.x, tx = t & 15, ty = t >> 4;
    int ldr = t >> 4, ldc = t & 15;
    int q0 = blockIdx.x * QPB;
    int m0 = q0 * KNB;

    if (t < 64){
        Pw[t]     = pw1[t];
        Pw[64+t]  = pw1[64+t];
        Pw[128+t] = pw1[128+t];
        Pw[192+t] = pb1[t];
    }
    if (t < RPB){
        int gq = q0 + t/KNB;
        int b  = gq >> 13;
        int jr = (b<<13) + g_idx[m0 + t];
        Jr[t] = jr;
        Rel[t*4+0] = pts[gq*3+0] - pts[(size_t)jr*3+0];
        Rel[t*4+1] = pts[gq*3+1] - pts[(size_t)jr*3+1];
        Rel[t*4+2] = pts[gq*3+2] - pts[(size_t)jr*3+2];
    }
    /* stage this block's 4 query rows of g_qw (1 float4 per thread) */
    *(float4*)&Qs[t*4] =
        *(const float4*)&g_qw[(size_t)(q0 + (t >> 6))*256 + (t & 63)*4];
    *(float4*)&Bs[ldr*68 + 4*ldc] = *(const float4*)&W2[ldr*320 + 4*ldc];
    __syncthreads();

    #pragma unroll
    for (int e = t; e < RPB*64; e += 256){
        int r = e >> 6, c = e & 63;
        float h = fmaf(Rel[r*4+0], Pw[c],
                  fmaf(Rel[r*4+1], Pw[64+c],
                  fmaf(Rel[r*4+2], Pw[128+c], Pw[192+c])));
        As[r*68 + c] = fmaxf(h, 0.f);
    }
    __syncthreads();

    int jr_r[5], qx_r[5];
    #pragma unroll
    for (int i=0;i<5;i++){
        int r = ty*5 + i;
        jr_r[i] = Jr[r];
        qx_r[i] = (r/KNB)*256;
    }

    float rsum[5] = {0.f,0.f,0.f,0.f,0.f};
    ull acc2[5][2];
    for (int it = 0; it < 20; it++){
        int nb = it >> 2, ch = (it & 3) * 16;
        int cur = it & 1;
        float4 nxt;
        if (it < 19){
            int nit = it + 1, nnb = nit >> 2, nch = (nit & 3) * 16;
            nxt = *(const float4*)&W2[(nch+ldr)*320 + nnb*64 + 4*ldc];
        }
        if ((it & 3) == 0){
            #pragma unroll
            for (int i=0;i<5;i++){ acc2[i][0] = 0ULL; acc2[i][1] = 0ULL; }
        }
        const float* Bc = &Bs[cur*1088];
        #pragma unroll
        for (int k4=0;k4<4;k4++){
            ulonglong2 b0 = *(const ulonglong2*)&Bc[(4*k4+0)*68 + 4*tx];
            ulonglong2 b1 = *(const ulonglong2*)&Bc[(4*k4+1)*68 + 4*tx];
            ulonglong2 b2 = *(const ulonglong2*)&Bc[(4*k4+2)*68 + 4*tx];
            ulonglong2 b3 = *(const ulonglong2*)&Bc[(4*k4+3)*68 + 4*tx];
            #pragma unroll
            for (int i=0;i<5;i++){
                float4 a = *(const float4*)&As[(ty*5+i)*68 + ch + 4*k4];
                ull ax = dup2(a.x), ay = dup2(a.y);
                ull az = dup2(a.z), aw = dup2(a.w);
                fma2(acc2[i][0], ax, b0.x); fma2(acc2[i][1], ax, b0.y);
                fma2(acc2[i][0], ay, b1.x); fma2(acc2[i][1], ay, b1.y);
                fma2(acc2[i][0], az, b2.x); fma2(acc2[i][1], az, b2.y);
                fma2(acc2[i][0], aw, b3.x); fma2(acc2[i][1], aw, b3.y);
            }
        }
        if ((it & 3) == 3){
            if (nb == 0){
                float4 pb = *(const float4*)&pb2[4*tx];
                #pragma unroll
                for (int i=0;i<5;i++){
                    int r = ty*5 + i;
                    float2 lo = unpack2(acc2[i][0]);
                    float2 hi = unpack2(acc2[i][1]);
                    float4 vv = *(const float4*)&g_v[(size_t)jr_r[i]*64 + 4*tx];
                    float4 o = make_float4(lo.x+pb.x+vv.x, lo.y+pb.y+vv.y,
                                           hi.x+pb.z+vv.z, hi.y+pb.w+vv.w);
                    *(float4*)&Vs[r*68 + 4*tx] = o;
                }
            } else {
                int cb = (nb-1)*64 + 4*tx;
                float4 cv  = *(const float4*)&CV[cb];
                float4 a2v = *(const float4*)&aw2[cb];
                #pragma unroll
                for (int i=0;i<5;i++){
                    float2 lo = unpack2(acc2[i][0]);
                    float2 hi = unpack2(acc2[i][1]);
                    float4 qv = *(const float4*)&Qs[qx_r[i] + cb];
                    float4 kv = *(const float4*)&g_kw[(size_t)jr_r[i]*256 + cb];
                    float h0 = fmaxf(lo.x + cv.x + qv.x - kv.x, 0.f);
                    float h1 = fmaxf(lo.y + cv.y + qv.y - kv.y, 0.f);
                    float h2 = fmaxf(hi.x + cv.z + qv.z - kv.z, 0.f);
                    float h3 = fmaxf(hi.y + cv.w + qv.w - kv.w, 0.f);
                    rsum[i] += h0*a2v.x + h1*a2v.y + h2*a2v.z + h3*a2v.w;
                }
            }
        }
        if (it < 19){
            *(float4*)&Bs[(cur^1)*1088 + ldr*68 + 4*ldc] = nxt;
            __syncthreads();
        }
    }
    float abias = ab2[0];
    #pragma unroll
    for (int i=0;i<5;i++){
        float v = rsum[i];
        v += __shfl_xor_sync(0xffffffffu, v, 8);
        v += __shfl_xor_sync(0xffffffffu, v, 4);
        v += __shfl_xor_sync(0xffffffffu, v, 2);
        v += __shfl_xor_sync(0xffffffffu, v, 1);
        if (tx == 0) Sim[ty*5+i] = v + abias;
    }
    __syncthreads();

    if (t < 128){
        int w = t >> 5, lane = t & 31;
        float s = (lane < KNB) ? Sim[w*KNB + lane] : -CUDART_INF_F;
        float m = s;
        #pragma unroll
        for (int off=16; off; off>>=1) m = fmaxf(m, __shfl_xor_sync(0xffffffffu, m, off));
        float e = (lane < KNB) ? expf(s - m) : 0.f;
        float sum = e;
        #pragma unroll
        for (int off=16; off; off>>=1) sum += __shfl_xor_sync(0xffffffffu, sum, off);
        float attn = e / sum;
        float acc0 = 0.f, acc1 = 0.f;
        #pragma unroll
        for (int kk=0; kk<KNB; kk++){
            float a = __shfl_sync(0xffffffffu, attn, kk);
            const float* vb = &Vs[(w*KNB + kk)*68];
            acc0 += a * vb[lane];
            acc1 += a * vb[32 + lane];
        }
        if (outsel){
            g_xb[(size_t)(q0+w)*64 + lane]      = acc0;
            g_xb[(size_t)(q0+w)*64 + 32 + lane] = acc1;
        } else {
            int b = (q0+w) >> 13;
            atomicMax(&g_pool[b*64 + lane],      fenc(acc0));
            atomicMax(&g_pool[b*64 + 32 + lane], fenc(acc1));
        }
    }
}

/* ---------------- head: pooled max -> fc1(relu) -> fc3 ------------ */
__global__ void head_kernel(
    const float* __restrict__ fc1w, const float* __restrict__ fc1b,
    const float* __restrict__ fc3w, const float* __restrict__ fc3b,
    float* __restrict__ out)
{
    __shared__ float sp[BATCH*64];
    __shared__ float sh[BATCH*32];
    int t = threadIdx.x;
    if (t < 128) sp[t] = fdec(g_pool[t]);
    __syncthreads();
    if (t < 64){
        int b = t >> 5, cc = t & 31;
        float s = fc1b[cc];
        for (int c=0;c<64;c++) s += sp[b*64+c] * fc1w[c*32 + cc];
        sh[b*32 + cc] = fmaxf(s, 0.f);
    }
    __syncthreads();
    if (t < 6){
        int b = t / 3, o = t % 3;
        float s = fc3b[o];
        for (int cc=0;cc<32;cc++) s += sh[b*32+cc] * fc3w[cc*3 + o];
        out[b*3 + o] = s;
    }
}

/* ------------------------------ launch ---------------------------- */
extern "C" void kernel_launch(void* const* d_in, const int* in_sizes, int n_in,
                              void* d_out, int out_size)
{
    (void)in_sizes; (void)n_in; (void)out_size;
    const float* pts = (const float*)d_in[0];
    float* out = (float*)d_out;

    cudaFuncSetAttribute(fused_attn_kernel,
                         cudaFuncAttributeMaxDynamicSharedMemorySize, SMF_TOT);
    cudaFuncSetAttribute(knn_pg_kernel,
                         cudaFuncAttributeMaxDynamicSharedMemorySize, CMB_SMEM);

    const float* W1[9] = {
        (const float*)d_in[3], (const float*)d_in[4], (const float*)d_in[5],
        (const float*)d_in[6], (const float*)d_in[7], (const float*)d_in[8],
        (const float*)d_in[9], (const float*)d_in[10], (const float*)d_in[11]};
    const float* W2[9] = {
        (const float*)d_in[12], (const float*)d_in[13], (const float*)d_in[14],
        (const float*)d_in[15], (const float*)d_in[16], (const float*)d_in[17],
        (const float*)d_in[18], (const float*)d_in[19], (const float*)d_in[20]};

    /* #1 prep(+pool reset); #2 knn+pgL1; #3 fused L1; #4 pg L2;
       #5 fused L2 (+pool atomics); #6 head                          */
    prep_kernel<<<450, 256>>>(W1[0], W1[3], W1[5], W1[4], W1[6],
                              W2[0], W2[3], W2[5], W2[4], W2[6]);
    knn_pg_kernel<<<2816, 256, CMB_SMEM>>>(pts, (const float*)d_in[1],
                                           (const float*)d_in[2]);
    fused_attn_kernel<<<BN_TOT/QPB, 256, SMF_TOT>>>(
        pts, W1[1], W1[2], W1[4], W1[7], W1[8], 0, 1);

    point_gemm_kernel<<<dim3(BN_TOT/64, 9), 256>>>();
    fused_attn_kernel<<<BN_TOT/QPB, 256, SMF_TOT>>>(
        pts, W2[1], W2[2], W2[4], W2[7], W2[8], 1, 0);

    head_kernel<<<1, 128>>>((const float*)d_in[21], (const float*)d_in[22],
                            (const float*)d_in[23], (const float*)d_in[24], out);
}